// round 15
// baseline (speedup 1.0000x reference)
#include <cuda_runtime.h>
#include <cuda_fp16.h>
#include <math.h>
#include <stdint.h>

// Problem dims (fixed)
#define Bdim 2
#define Sdim 2048
#define Ddim 1024
#define Vdim 50257
#define VPAD 50304            // 393*128, multiple of 8
#define NGRP (VPAD / 8)       // 6288
#define Mrows (Bdim * Sdim)   // 4096
#define LMROWBLK 13           // blocks per W_lm row (13*512 groups >= 6288)

// ---------------------------------------------------------------------------
// Scratch (device globals — no runtime allocation allowed)
// ---------------------------------------------------------------------------
__device__ float  g_h[(size_t)Mrows * Ddim];
__device__ __half g_qkv16[(size_t)Mrows * 3 * Ddim];
__device__ __half g_x16[(size_t)Mrows * Ddim];
__device__ __half g_ao16[(size_t)Mrows * Ddim];
__device__ __half g_fc16[(size_t)Mrows * 4 * Ddim];
__device__ __half g_wattn16[(size_t)Ddim * 3 * Ddim];
__device__ __half g_wap16[(size_t)Ddim * Ddim];
__device__ __half g_wfc16[(size_t)Ddim * 4 * Ddim];
__device__ __half g_wproj16[(size_t)4 * Ddim * Ddim];
__device__ __half g_wlm16[(size_t)Ddim * VPAD];

__device__ __forceinline__ uint32_t smem_u32(const void* p) {
    uint32_t a;
    asm("{ .reg .u64 t; cvta.to.shared.u64 t, %1; cvt.u32.u64 %0, t; }"
        : "=r"(a) : "l"(p));
    return a;
}
__device__ __forceinline__ float gelu_new_f(float x) {
    float t = tanhf(0.7978845608028654f * (x + 0.044715f * x * x * x));
    return 0.5f * x * (1.0f + t);
}

#define LDSM4(r0, r1, r2, r3, a) \
    asm volatile("ldmatrix.sync.aligned.m8n8.x4.shared.b16 {%0,%1,%2,%3}, [%4];" \
        : "=r"(r0), "=r"(r1), "=r"(r2), "=r"(r3) : "r"(a))
#define LDSM4T(r0, r1, r2, r3, a) \
    asm volatile("ldmatrix.sync.aligned.m8n8.x4.trans.shared.b16 {%0,%1,%2,%3}, [%4];" \
        : "=r"(r0), "=r"(r1), "=r"(r2), "=r"(r3) : "r"(a))
#define MMA16816(d, a, b0, b1) \
    asm volatile("mma.sync.aligned.m16n8k16.row.col.f32.f16.f16.f32 " \
        "{%0,%1,%2,%3}, {%4,%5,%6,%7}, {%8,%9}, {%0,%1,%2,%3};" \
        : "+f"((d)[0]), "+f"((d)[1]), "+f"((d)[2]), "+f"((d)[3]) \
        : "r"((a)[0]), "r"((a)[1]), "r"((a)[2]), "r"((a)[3]), \
          "r"(b0), "r"(b1))

// ---------------------------------------------------------------------------
// Conversion helpers
// ---------------------------------------------------------------------------
__device__ __forceinline__ void conv16_chunk(
    const float* __restrict__ src, __half* __restrict__ dst, size_t i)
{
    float4 a0 = *(const float4*)(src + i);
    float4 a1 = *(const float4*)(src + i + 4);
    float4 a2 = *(const float4*)(src + i + 8);
    float4 a3 = *(const float4*)(src + i + 12);
    __half h[16];
    h[0]  = __float2half_rn(a0.x); h[1]  = __float2half_rn(a0.y);
    h[2]  = __float2half_rn(a0.z); h[3]  = __float2half_rn(a0.w);
    h[4]  = __float2half_rn(a1.x); h[5]  = __float2half_rn(a1.y);
    h[6]  = __float2half_rn(a1.z); h[7]  = __float2half_rn(a1.w);
    h[8]  = __float2half_rn(a2.x); h[9]  = __float2half_rn(a2.y);
    h[10] = __float2half_rn(a2.z); h[11] = __float2half_rn(a2.w);
    h[12] = __float2half_rn(a3.x); h[13] = __float2half_rn(a3.y);
    h[14] = __float2half_rn(a3.z); h[15] = __float2half_rn(a3.w);
    *(uint4*)(dst + i)     = *(uint4*)h;
    *(uint4*)(dst + i + 8) = *(uint4*)(h + 8);
}

__device__ __forceinline__ void convlm_group(
    const float* __restrict__ src, __half* __restrict__ dst, int k, int g)
{
    int n = g * 8;
    size_t base = (size_t)k * Vdim + n;
    int rc = Vdim - n;
    __half h[8];
    #pragma unroll
    for (int j = 0; j < 8; j++) h[j] = __half(0.f);

    if (rc >= 8) {
        int p = k & 3;
        size_t a0 = base - p;
        if (p == 0) {
            float4 w0 = *(const float4*)(src + a0);
            float4 w1 = *(const float4*)(src + a0 + 4);
            h[0] = __float2half_rn(w0.x); h[1] = __float2half_rn(w0.y);
            h[2] = __float2half_rn(w0.z); h[3] = __float2half_rn(w0.w);
            h[4] = __float2half_rn(w1.x); h[5] = __float2half_rn(w1.y);
            h[6] = __float2half_rn(w1.z); h[7] = __float2half_rn(w1.w);
        } else {
            float4 w0 = *(const float4*)(src + a0);
            float4 w1 = *(const float4*)(src + a0 + 4);
            float4 w2 = *(const float4*)(src + a0 + 8);
            float wnd[12] = {w0.x, w0.y, w0.z, w0.w, w1.x, w1.y, w1.z, w1.w,
                             w2.x, w2.y, w2.z, w2.w};
            switch (p) {
            case 1:
                #pragma unroll
                for (int j = 0; j < 8; j++) h[j] = __float2half_rn(wnd[1 + j]);
                break;
            case 2:
                #pragma unroll
                for (int j = 0; j < 8; j++) h[j] = __float2half_rn(wnd[2 + j]);
                break;
            default:
                #pragma unroll
                for (int j = 0; j < 8; j++) h[j] = __float2half_rn(wnd[3 + j]);
                break;
            }
        }
    } else if (rc > 0) {
        for (int j = 0; j < rc; j++) h[j] = __float2half_rn(src[base + j]);
    }
    *(uint4*)(dst + (size_t)k * VPAD + n) = *(uint4*)h;
}

// ---------------------------------------------------------------------------
// Mega-conversion: ALL weight fp32->fp16 conversions in one launch.
// ---------------------------------------------------------------------------
#define CONV_GRID (3072 + Ddim * LMROWBLK)   // 16384

__global__ void __launch_bounds__(256) convall_kernel(
    const float* __restrict__ Wattn, const float* __restrict__ Wap,
    const float* __restrict__ Wfc,   const float* __restrict__ Wproj,
    const float* __restrict__ Wlm,
    __half* __restrict__ wattn16, __half* __restrict__ wap16,
    __half* __restrict__ wfc16,   __half* __restrict__ wproj16,
    __half* __restrict__ wlm16)
{
    int b = blockIdx.x;
    if (b < 3072) {
        const float* src;
        __half* dst;
        int lb;
        if (b < 768)       { src = Wattn; dst = wattn16; lb = b; }
        else if (b < 1024) { src = Wap;   dst = wap16;   lb = b - 768; }
        else if (b < 2048) { src = Wfc;   dst = wfc16;   lb = b - 1024; }
        else               { src = Wproj; dst = wproj16; lb = b - 2048; }
        size_t i = ((size_t)lb * 256 + threadIdx.x) * 16;
        conv16_chunk(src, dst, i);
    } else {
        int bb = b - 3072;
        int k  = bb / LMROWBLK;
        int gb = bb % LMROWBLK;
        int g0 = (gb * 256 + threadIdx.x) * 2;
        if (g0 < NGRP)     convlm_group(Wlm, wlm16, k, g0);
        if (g0 + 1 < NGRP) convlm_group(Wlm, wlm16, k, g0 + 1);
    }
}

// ---------------------------------------------------------------------------
// Fused embedding + LayerNorm1: h = wte[id]+wpe[s]; x16 = ln1(h) (fp16)
// ---------------------------------------------------------------------------
__global__ void __launch_bounds__(256) embed_ln_kernel(
    const int* __restrict__ ids, const float* __restrict__ wte,
    const float* __restrict__ wpe, const float* __restrict__ g,
    const float* __restrict__ b, float* __restrict__ h,
    __half* __restrict__ out)
{
    int row = blockIdx.x;
    int s0  = row & (Sdim - 1);
    int id  = ids[row];
    int t = threadIdx.x;
    float4 a = ((const float4*)(wte + (size_t)id * Ddim))[t];
    float4 p = ((const float4*)(wpe + (size_t)s0 * Ddim))[t];
    float4 v = make_float4(a.x + p.x, a.y + p.y, a.z + p.z, a.w + p.w);
    ((float4*)(h + (size_t)row * Ddim))[t] = v;

    float s = v.x + v.y + v.z + v.w;
    float q = v.x * v.x + v.y * v.y + v.z * v.z + v.w * v.w;
    __shared__ float rs[8], rq[8];
    #pragma unroll
    for (int o = 16; o > 0; o >>= 1) {
        s += __shfl_xor_sync(0xffffffffu, s, o);
        q += __shfl_xor_sync(0xffffffffu, q, o);
    }
    if ((t & 31) == 0) { rs[t >> 5] = s; rq[t >> 5] = q; }
    __syncthreads();
    if (t == 0) {
        float S = 0.f, Q = 0.f;
        #pragma unroll
        for (int i = 0; i < 8; i++) { S += rs[i]; Q += rq[i]; }
        rs[0] = S; rq[0] = Q;
    }
    __syncthreads();
    float mu   = rs[0] * (1.f / Ddim);
    float var  = rq[0] * (1.f / Ddim) - mu * mu;
    float rstd = rsqrtf(var + 1e-5f);
    float4 gg = ((const float4*)g)[t];
    float4 bb = ((const float4*)b)[t];
    __half2* o = (__half2*)(out + (size_t)row * Ddim + t * 4);
    o[0] = __floats2half2_rn((v.x - mu) * rstd * gg.x + bb.x,
                             (v.y - mu) * rstd * gg.y + bb.y);
    o[1] = __floats2half2_rn((v.z - mu) * rstd * gg.z + bb.z,
                             (v.w - mu) * rstd * gg.w + bb.w);
}

// ---------------------------------------------------------------------------
// LayerNorm (fp32 in) -> fp16 out (for ln2 / lnf)
// ---------------------------------------------------------------------------
__global__ void __launch_bounds__(256) ln16_kernel(
    const float* __restrict__ in, const float* __restrict__ g,
    const float* __restrict__ b, __half* __restrict__ out)
{
    int row = blockIdx.x;
    int t = threadIdx.x;
    const float4* xp = (const float4*)(in + (size_t)row * Ddim);
    float4 v = xp[t];
    float s = v.x + v.y + v.z + v.w;
    float q = v.x * v.x + v.y * v.y + v.z * v.z + v.w * v.w;
    __shared__ float rs[8], rq[8];
    #pragma unroll
    for (int o = 16; o > 0; o >>= 1) {
        s += __shfl_xor_sync(0xffffffffu, s, o);
        q += __shfl_xor_sync(0xffffffffu, q, o);
    }
    if ((t & 31) == 0) { rs[t >> 5] = s; rq[t >> 5] = q; }
    __syncthreads();
    if (t == 0) {
        float S = 0.f, Q = 0.f;
        #pragma unroll
        for (int i = 0; i < 8; i++) { S += rs[i]; Q += rq[i]; }
        rs[0] = S; rq[0] = Q;
    }
    __syncthreads();
    float mu   = rs[0] * (1.f / Ddim);
    float var  = rq[0] * (1.f / Ddim) - mu * mu;
    float rstd = rsqrtf(var + 1e-5f);
    float4 gg = ((const float4*)g)[t];
    float4 bb = ((const float4*)b)[t];
    __half2* o = (__half2*)(out + (size_t)row * Ddim + t * 4);
    o[0] = __floats2half2_rn((v.x - mu) * rstd * gg.x + bb.x,
                             (v.y - mu) * rstd * gg.y + bb.y);
    o[1] = __floats2half2_rn((v.z - mu) * rstd * gg.z + bb.z,
                             (v.w - mu) * rstd * gg.w + bb.w);
}

// ---------------------------------------------------------------------------
// fp16 GEMM (fp32 acc): 128 threads (4 warps 2x2), CTA 128x128, warp 64x64,
// 3-stage cp.async ring, 2 CTAs/SM. (verified R11 — used for ALL GEMMs)
// ---------------------------------------------------------------------------
#define APh 40
#define BPh 136
#define ASZ (128 * APh)
#define BSZ (32 * BPh)
#define STGh (ASZ + BSZ)
#define GSMEM (3 * STGh * 2)     // 56832 B

template<bool HAS_BIAS, bool DO_GELU, bool HAS_RES, bool OUT16>
__global__ void __launch_bounds__(128, 2) gemm16_kernel(
    const __half* __restrict__ A, const __half* __restrict__ W,
    const float* __restrict__ bias, const float* __restrict__ res,
    void* __restrict__ Cv, int M, int N, int K, int ldw)
{
    extern __shared__ __half sh[];
    const uint32_t sb = smem_u32(sh);

    const int tid  = threadIdx.x;
    const int wid  = tid >> 5;
    const int lane = tid & 31;
    const int wm   = (wid >> 1) * 64;
    const int wn   = (wid & 1) * 64;
    const int lr   = lane >> 2;
    const int lc   = lane & 3;
    const int bm   = blockIdx.x * 128;
    const int bn   = blockIdx.y * 128;

    const int am  = tid >> 2, akc = tid & 3;
    const int bk  = tid >> 4, bnc = tid & 15;

    auto issue = [&](int kb) {
        const int s = kb % 3;
        const uint32_t as = sb + (uint32_t)(s * STGh) * 2;
        const uint32_t bs = as + ASZ * 2;
        const int k0 = kb * 32;
        #pragma unroll
        for (int i = 0; i < 4; i++) {
            int m = am + i * 32;
            const __half* src = A + (size_t)(bm + m) * K + k0 + akc * 8;
            uint32_t dst = as + (uint32_t)(m * APh + akc * 8) * 2;
            asm volatile("cp.async.cg.shared.global [%0], [%1], 16;"
                         :: "r"(dst), "l"(src));
        }
        #pragma unroll
        for (int i = 0; i < 4; i++) {
            int k = bk + i * 8;
            const __half* src = W + (size_t)(k0 + k) * ldw + bn + bnc * 8;
            uint32_t dst = bs + (uint32_t)(k * BPh + bnc * 8) * 2;
            asm volatile("cp.async.cg.shared.global [%0], [%1], 16;"
                         :: "r"(dst), "l"(src));
        }
        asm volatile("cp.async.commit_group;");
    };

    float acc[4][8][4];
    #pragma unroll
    for (int i = 0; i < 4; i++)
        #pragma unroll
        for (int j = 0; j < 8; j++)
            #pragma unroll
            for (int e = 0; e < 4; e++) acc[i][j][e] = 0.f;

    const int nk = K / 32;
    issue(0);
    issue(1);

    for (int kb = 0; kb < nk; kb++) {
        if (kb + 1 < nk) asm volatile("cp.async.wait_group 1;");
        else             asm volatile("cp.async.wait_group 0;");
        __syncthreads();
        if (kb + 2 < nk) issue(kb + 2);

        const int s = kb % 3;
        const uint32_t as = sb + (uint32_t)(s * STGh) * 2;
        const uint32_t bs = as + ASZ * 2;

        #pragma unroll
        for (int ks = 0; ks < 2; ks++) {
            const int kk = ks * 16;
            uint32_t afr[4][4];
            #pragma unroll
            for (int mt = 0; mt < 4; mt++) {
                uint32_t a = as + (uint32_t)((wm + mt * 16 + (lane & 15)) * APh
                                             + kk + 8 * (lane >> 4)) * 2;
                LDSM4(afr[mt][0], afr[mt][1], afr[mt][2], afr[mt][3], a);
            }
            uint32_t bfr[8][2];
            #pragma unroll
            for (int p = 0; p < 4; p++) {
                int ntp = p * 2;
                uint32_t a = bs + (uint32_t)((kk + (lane & 7) + 8 * ((lane >> 3) & 1)) * BPh
                                             + wn + (ntp + (lane >> 4)) * 8) * 2;
                LDSM4T(bfr[ntp][0], bfr[ntp][1], bfr[ntp + 1][0], bfr[ntp + 1][1], a);
            }
            #pragma unroll
            for (int mt = 0; mt < 4; mt++)
                #pragma unroll
                for (int nt = 0; nt < 8; nt++)
                    MMA16816(acc[mt][nt], afr[mt], bfr[nt][0], bfr[nt][1]);
        }
    }

    float* Cf = (float*)Cv;
    __half* Ch = (__half*)Cv;
    const bool neven = ((N & 1) == 0);
    #pragma unroll
    for (int mt = 0; mt < 4; mt++) {
        int row0 = bm + wm + mt * 16 + lr;
        #pragma unroll
        for (int nt = 0; nt < 8; nt++) {
            int col0 = bn + wn + nt * 8 + lc * 2;
            #pragma unroll
            for (int half_ = 0; half_ < 2; half_++) {
                int row = row0 + half_ * 8;
                float v0 = acc[mt][nt][half_ * 2];
                float v1 = acc[mt][nt][half_ * 2 + 1];
                if (HAS_BIAS) { v0 += bias[col0]; v1 += bias[col0 + 1]; }
                if (DO_GELU)  { v0 = gelu_new_f(v0); v1 = gelu_new_f(v1); }
                size_t off = (size_t)row * (size_t)N + col0;
                if (HAS_RES) {
                    if (col0 < N)     v0 += res[off];
                    if (col0 + 1 < N) v1 += res[off + 1];
                }
                if (neven && col0 + 1 < N) {
                    if (OUT16) *(__half2*)(Ch + off) = __floats2half2_rn(v0, v1);
                    else       *(float2*)(Cf + off) = make_float2(v0, v1);
                } else {
                    if (col0 < N) {
                        if (OUT16) Ch[off] = __float2half_rn(v0);
                        else       Cf[off] = v0;
                    }
                    if (col0 + 1 < N) {
                        if (OUT16) Ch[off + 1] = __float2half_rn(v1);
                        else       Cf[off + 1] = v1;
                    }
                }
            }
        }
    }
}

// ---------------------------------------------------------------------------
// Tensor-core flash attention (causal), fp16 mma, fp32 softmax.
// NOW __launch_bounds__(256, 2): cap regs at 128 -> 2 CTAs/SM (smem 55.3KB*2).
// ---------------------------------------------------------------------------
#define FP 72
#define FLASH16_SMEM ((128 * FP + 4 * 64 * FP) * 2)   // 55296 B

__global__ void __launch_bounds__(256, 2) flashtc_kernel(
    const __half* __restrict__ qkv, __half* __restrict__ ao)
{
    extern __shared__ __half fsm[];
    const uint32_t sb   = smem_u32(fsm);
    const uint32_t qs_b = sb;
    const uint32_t ks_b = sb + 128 * FP * 2;
    const uint32_t vs_b = ks_b + 2 * 64 * FP * 2;
    __half* Qs = fsm;

    const int qt  = (int)gridDim.x - 1 - (int)blockIdx.x;
    const int bh  = blockIdx.y;
    const int b   = bh >> 4;
    const int h   = bh & 15;
    const int tid = threadIdx.x;
    const int wid = tid >> 5;
    const int lane = tid & 31;
    const int lr  = lane >> 2;
    const int lc  = lane & 3;
    const size_t base = (size_t)b * Sdim * 3072 + (size_t)h * 64;

    const __half2 kscale = __floats2half2_rn(0.125f, 0.125f);
    #pragma unroll
    for (int i = 0; i < 4; i++) {
        int task = tid + i * 256;
        int row = task >> 3, ch = task & 7;
        uint4 u = *(const uint4*)(qkv + base + (size_t)(qt * 128 + row) * 3072 + ch * 8);
        __half2* hp = (__half2*)&u;
        #pragma unroll
        for (int j = 0; j < 4; j++) hp[j] = __hmul2(hp[j], kscale);
        *(uint4*)&Qs[row * FP + ch * 8] = u;
    }

    auto issue = [&](int kt) {
        const int s = kt & 1;
        #pragma unroll
        for (int i = 0; i < 2; i++) {
            int task = tid + i * 256;
            int row = task >> 3, ch = task & 7;
            const __half* sk = qkv + base + 1024 + (size_t)(kt * 64 + row) * 3072 + ch * 8;
            const __half* sv = qkv + base + 2048 + (size_t)(kt * 64 + row) * 3072 + ch * 8;
            uint32_t dk = ks_b + (uint32_t)(s * 64 * FP + row * FP + ch * 8) * 2;
            uint32_t dv = vs_b + (uint32_t)(s * 64 * FP + row * FP + ch * 8) * 2;
            asm volatile("cp.async.cg.shared.global [%0], [%1], 16;" :: "r"(dk), "l"(sk));
            asm volatile("cp.async.cg.shared.global [%0], [%1], 16;" :: "r"(dv), "l"(sv));
        }
        asm volatile("cp.async.commit_group;");
    };

    const int ktn = 2 * qt + 2;
    issue(0);
    issue(1);
    __syncthreads();

    uint32_t qf[4][4];
    {
        int row = wid * 16 + (lane & 15);
        int cof = 8 * (lane >> 4);
        #pragma unroll
        for (int kc = 0; kc < 4; kc++) {
            uint32_t a = qs_b + (uint32_t)(row * FP + kc * 16 + cof) * 2;
            LDSM4(qf[kc][0], qf[kc][1], qf[kc][2], qf[kc][3], a);
        }
    }

    float o[8][4];
    #pragma unroll
    for (int nt = 0; nt < 8; nt++)
        #pragma unroll
        for (int e = 0; e < 4; e++) o[nt][e] = 0.f;
    float m0 = -1e30f, m1 = -1e30f, l0 = 0.f, l1 = 0.f;
    const int qg0 = qt * 128 + wid * 16 + lr;

    for (int kt = 0; kt < ktn; kt++) {
        if (kt + 1 < ktn) asm volatile("cp.async.wait_group 1;");
        else              asm volatile("cp.async.wait_group 0;");
        __syncthreads();

        const int s = kt & 1;
        const uint32_t kb_ = ks_b + (uint32_t)(s * 64 * FP) * 2;
        const uint32_t vb_ = vs_b + (uint32_t)(s * 64 * FP) * 2;

        float sc[8][4];
        #pragma unroll
        for (int nt = 0; nt < 8; nt++)
            #pragma unroll
            for (int e = 0; e < 4; e++) sc[nt][e] = 0.f;
        const int krow = (lane & 7) + 8 * (lane >> 4);
        const int koff = 8 * ((lane >> 3) & 1);
        #pragma unroll
        for (int kc = 0; kc < 4; kc++) {
            #pragma unroll
            for (int np = 0; np < 4; np++) {
                uint32_t a = kb_ + (uint32_t)((np * 16 + krow) * FP + kc * 16 + koff) * 2;
                uint32_t b0, b1, b2, b3;
                LDSM4(b0, b1, b2, b3, a);
                MMA16816(sc[2 * np], qf[kc], b0, b1);
                MMA16816(sc[2 * np + 1], qf[kc], b2, b3);
            }
        }

        const bool diag = (kt >= 2 * qt);
        float tmax0 = -1e30f, tmax1 = -1e30f;
        #pragma unroll
        for (int nt = 0; nt < 8; nt++) {
            #pragma unroll
            for (int e = 0; e < 4; e++) {
                if (diag) {
                    int key = kt * 64 + nt * 8 + 2 * lc + (e & 1);
                    int qg  = qg0 + (e >= 2 ? 8 : 0);
                    if (key > qg) sc[nt][e] = -1e30f;
                }
                if (e < 2) tmax0 = fmaxf(tmax0, sc[nt][e]);
                else       tmax1 = fmaxf(tmax1, sc[nt][e]);
            }
        }
        tmax0 = fmaxf(tmax0, __shfl_xor_sync(0xffffffffu, tmax0, 1));
        tmax0 = fmaxf(tmax0, __shfl_xor_sync(0xffffffffu, tmax0, 2));
        tmax1 = fmaxf(tmax1, __shfl_xor_sync(0xffffffffu, tmax1, 1));
        tmax1 = fmaxf(tmax1, __shfl_xor_sync(0xffffffffu, tmax1, 2));
        float mn0 = fmaxf(m0, tmax0), mn1 = fmaxf(m1, tmax1);
        float cr0 = __expf(m0 - mn0), cr1 = __expf(m1 - mn1);
        float ps0 = 0.f, ps1 = 0.f;
        #pragma unroll
        for (int nt = 0; nt < 8; nt++) {
            sc[nt][0] = __expf(sc[nt][0] - mn0);
            sc[nt][1] = __expf(sc[nt][1] - mn0);
            sc[nt][2] = __expf(sc[nt][2] - mn1);
            sc[nt][3] = __expf(sc[nt][3] - mn1);
            ps0 += sc[nt][0] + sc[nt][1];
            ps1 += sc[nt][2] + sc[nt][3];
        }
        ps0 += __shfl_xor_sync(0xffffffffu, ps0, 1);
        ps0 += __shfl_xor_sync(0xffffffffu, ps0, 2);
        ps1 += __shfl_xor_sync(0xffffffffu, ps1, 1);
        ps1 += __shfl_xor_sync(0xffffffffu, ps1, 2);
        l0 = l0 * cr0 + ps0;  m0 = mn0;
        l1 = l1 * cr1 + ps1;  m1 = mn1;
        #pragma unroll
        for (int nt = 0; nt < 8; nt++) {
            o[nt][0] *= cr0; o[nt][1] *= cr0;
            o[nt][2] *= cr1; o[nt][3] *= cr1;
        }

        uint32_t pf[4][4];
        #pragma unroll
        for (int kc = 0; kc < 4; kc++) {
            __half2 h0 = __floats2half2_rn(sc[2 * kc][0], sc[2 * kc][1]);
            __half2 h1 = __floats2half2_rn(sc[2 * kc][2], sc[2 * kc][3]);
            __half2 h2 = __floats2half2_rn(sc[2 * kc + 1][0], sc[2 * kc + 1][1]);
            __half2 h3 = __floats2half2_rn(sc[2 * kc + 1][2], sc[2 * kc + 1][3]);
            pf[kc][0] = *(uint32_t*)&h0;
            pf[kc][1] = *(uint32_t*)&h1;
            pf[kc][2] = *(uint32_t*)&h2;
            pf[kc][3] = *(uint32_t*)&h3;
        }

        const int vrow = (lane & 7) + 8 * ((lane >> 3) & 1);
        const int vcof = (lane >> 4);
        #pragma unroll
        for (int kc = 0; kc < 4; kc++) {
            #pragma unroll
            for (int np = 0; np < 4; np++) {
                uint32_t a = vb_ + (uint32_t)((kc * 16 + vrow) * FP + (np * 2 + vcof) * 8) * 2;
                uint32_t b0, b1, b2, b3;
                LDSM4T(b0, b1, b2, b3, a);
                MMA16816(o[2 * np], pf[kc], b0, b1);
                MMA16816(o[2 * np + 1], pf[kc], b2, b3);
            }
        }

        if (kt + 2 < ktn) {
            __syncthreads();
            issue(kt + 2);
        }
    }

    float i0 = 1.f / l0, i1 = 1.f / l1;
    size_t r0 = (size_t)(b * Sdim + qt * 128 + wid * 16 + lr) * Ddim + h * 64;
    size_t r1 = r0 + 8 * Ddim;
    #pragma unroll
    for (int nt = 0; nt < 8; nt++) {
        int col = nt * 8 + 2 * lc;
        *(__half2*)(ao + r0 + col) = __floats2half2_rn(o[nt][0] * i0, o[nt][1] * i0);
        *(__half2*)(ao + r1 + col) = __floats2half2_rn(o[nt][2] * i1, o[nt][3] * i1);
    }
}

// ---------------------------------------------------------------------------
// Launch sequence
// ---------------------------------------------------------------------------
extern "C" void kernel_launch(void* const* d_in, const int* in_sizes, int n_in,
                              void* d_out, int out_size)
{
    const int*   ids    = (const int*)d_in[0];
    const float* wte    = (const float*)d_in[1];
    const float* wpe    = (const float*)d_in[2];
    const float* ln1_g  = (const float*)d_in[3];
    const float* ln1_b  = (const float*)d_in[4];
    const float* W_attn = (const float*)d_in[5];
    const float* b_attn = (const float*)d_in[6];
    const float* W_ap   = (const float*)d_in[7];
    const float* b_ap   = (const float*)d_in[8];
    const float* ln2_g  = (const float*)d_in[9];
    const float* ln2_b  = (const float*)d_in[10];
    const float* W_fc   = (const float*)d_in[11];
    const float* b_fc   = (const float*)d_in[12];
    const float* W_proj = (const float*)d_in[13];
    const float* b_proj = (const float*)d_in[14];
    const float* lnf_g  = (const float*)d_in[15];
    const float* lnf_b  = (const float*)d_in[16];
    const float* W_lm   = (const float*)d_in[17];
    float* out = (float*)d_out;

    float *h;
    __half *qkv16, *x16, *ao16, *fc16, *wattn16, *wap16, *wfc16, *wproj16, *wlm16;
    cudaGetSymbolAddress((void**)&h,       g_h);
    cudaGetSymbolAddress((void**)&qkv16,   g_qkv16);
    cudaGetSymbolAddress((void**)&x16,     g_x16);
    cudaGetSymbolAddress((void**)&ao16,    g_ao16);
    cudaGetSymbolAddress((void**)&fc16,    g_fc16);
    cudaGetSymbolAddress((void**)&wattn16, g_wattn16);
    cudaGetSymbolAddress((void**)&wap16,   g_wap16);
    cudaGetSymbolAddress((void**)&wfc16,   g_wfc16);
    cudaGetSymbolAddress((void**)&wproj16, g_wproj16);
    cudaGetSymbolAddress((void**)&wlm16,   g_wlm16);

    cudaFuncSetAttribute(flashtc_kernel,
                         cudaFuncAttributeMaxDynamicSharedMemorySize, FLASH16_SMEM);
    cudaFuncSetAttribute(gemm16_kernel<true, false, false, true>,
                         cudaFuncAttributeMaxDynamicSharedMemorySize, GSMEM);
    cudaFuncSetAttribute(gemm16_kernel<true, false, true, false>,
                         cudaFuncAttributeMaxDynamicSharedMemorySize, GSMEM);
    cudaFuncSetAttribute(gemm16_kernel<true, true, false, true>,
                         cudaFuncAttributeMaxDynamicSharedMemorySize, GSMEM);
    cudaFuncSetAttribute(gemm16_kernel<false, false, false, false>,
                         cudaFuncAttributeMaxDynamicSharedMemorySize, GSMEM);

    // all weight conversions in one launch
    convall_kernel<<<CONV_GRID, 256>>>(W_attn, W_ap, W_fc, W_proj, W_lm,
                                       wattn16, wap16, wfc16, wproj16, wlm16);
    // h = wte[ids]+wpe ; x16 = ln1(h)
    embed_ln_kernel<<<Mrows, 256>>>(ids, wte, wpe, ln1_g, ln1_b, h, x16);
    // qkv = x @ W_attn + b_attn (fp16 out)   N=3072
    gemm16_kernel<true, false, false, true><<<dim3(32, 24), 128, GSMEM>>>(
        x16, wattn16, b_attn, nullptr, qkv16, Mrows, 3 * Ddim, Ddim, 3 * Ddim);
    flashtc_kernel<<<dim3(16, 32), 256, FLASH16_SMEM>>>(qkv16, ao16);
    // h = h + ao @ W_ap + b_ap               N=1024
    gemm16_kernel<true, false, true, false><<<dim3(32, 8), 128, GSMEM>>>(
        ao16, wap16, b_ap, h, h, Mrows, Ddim, Ddim, Ddim);
    ln16_kernel<<<Mrows, 256>>>(h, ln2_g, ln2_b, x16);
    // fc = gelu(x @ W_fc + b_fc) (fp16 out)  N=4096
    gemm16_kernel<true, true, false, true><<<dim3(32, 32), 128, GSMEM>>>(
        x16, wfc16, b_fc, nullptr, fc16, Mrows, 4 * Ddim, Ddim, 4 * Ddim);
    // h = h + fc @ W_proj + b_proj           N=1024
    gemm16_kernel<true, false, true, false><<<dim3(32, 8), 128, GSMEM>>>(
        fc16, wproj16, b_proj, h, h, Mrows, Ddim, 4 * Ddim, Ddim);
    ln16_kernel<<<Mrows, 256>>>(h, lnf_g, lnf_b, x16);
    // logits = x @ W_lm (fp32 out)           N=50257
    gemm16_kernel<false, false, false, false><<<dim3(32, 393), 128, GSMEM>>>(
        x16, wlm16, nullptr, nullptr, out, Mrows, Vdim, Ddim, VPAD);
}

// round 16
// speedup vs baseline: 1.0051x; 1.0051x over previous
#include <cuda_runtime.h>
#include <cuda_fp16.h>
#include <math.h>
#include <stdint.h>

// Problem dims (fixed)
#define Bdim 2
#define Sdim 2048
#define Ddim 1024
#define Vdim 50257
#define VPAD 50304            // 393*128, multiple of 8
#define NGRP (VPAD / 8)       // 6288
#define Mrows (Bdim * Sdim)   // 4096
#define LMROWBLK 13           // blocks per W_lm row (13*512 groups >= 6288)

// ---------------------------------------------------------------------------
// Scratch (device globals — no runtime allocation allowed)
// ---------------------------------------------------------------------------
__device__ float  g_h[(size_t)Mrows * Ddim];
__device__ __half g_qkv16[(size_t)Mrows * 3 * Ddim];
__device__ __half g_x16[(size_t)Mrows * Ddim];
__device__ __half g_ao16[(size_t)Mrows * Ddim];
__device__ __half g_fc16[(size_t)Mrows * 4 * Ddim];
__device__ __half g_wattn16[(size_t)Ddim * 3 * Ddim];
__device__ __half g_wap16[(size_t)Ddim * Ddim];
__device__ __half g_wfc16[(size_t)Ddim * 4 * Ddim];
__device__ __half g_wproj16[(size_t)4 * Ddim * Ddim];
__device__ __half g_wlm16[(size_t)Ddim * VPAD];

__device__ __forceinline__ uint32_t smem_u32(const void* p) {
    uint32_t a;
    asm("{ .reg .u64 t; cvta.to.shared.u64 t, %1; cvt.u32.u64 %0, t; }"
        : "=r"(a) : "l"(p));
    return a;
}
__device__ __forceinline__ float gelu_new_f(float x) {
    float t = tanhf(0.7978845608028654f * (x + 0.044715f * x * x * x));
    return 0.5f * x * (1.0f + t);
}

#define LDSM4(r0, r1, r2, r3, a) \
    asm volatile("ldmatrix.sync.aligned.m8n8.x4.shared.b16 {%0,%1,%2,%3}, [%4];" \
        : "=r"(r0), "=r"(r1), "=r"(r2), "=r"(r3) : "r"(a))
#define LDSM4T(r0, r1, r2, r3, a) \
    asm volatile("ldmatrix.sync.aligned.m8n8.x4.trans.shared.b16 {%0,%1,%2,%3}, [%4];" \
        : "=r"(r0), "=r"(r1), "=r"(r2), "=r"(r3) : "r"(a))
#define MMA16816(d, a, b0, b1) \
    asm volatile("mma.sync.aligned.m16n8k16.row.col.f32.f16.f16.f32 " \
        "{%0,%1,%2,%3}, {%4,%5,%6,%7}, {%8,%9}, {%0,%1,%2,%3};" \
        : "+f"((d)[0]), "+f"((d)[1]), "+f"((d)[2]), "+f"((d)[3]) \
        : "r"((a)[0]), "r"((a)[1]), "r"((a)[2]), "r"((a)[3]), \
          "r"(b0), "r"(b1))

// ---------------------------------------------------------------------------
// Conversion helpers
// ---------------------------------------------------------------------------
__device__ __forceinline__ void conv16_chunk(
    const float* __restrict__ src, __half* __restrict__ dst, size_t i)
{
    float4 a0 = *(const float4*)(src + i);
    float4 a1 = *(const float4*)(src + i + 4);
    float4 a2 = *(const float4*)(src + i + 8);
    float4 a3 = *(const float4*)(src + i + 12);
    __half h[16];
    h[0]  = __float2half_rn(a0.x); h[1]  = __float2half_rn(a0.y);
    h[2]  = __float2half_rn(a0.z); h[3]  = __float2half_rn(a0.w);
    h[4]  = __float2half_rn(a1.x); h[5]  = __float2half_rn(a1.y);
    h[6]  = __float2half_rn(a1.z); h[7]  = __float2half_rn(a1.w);
    h[8]  = __float2half_rn(a2.x); h[9]  = __float2half_rn(a2.y);
    h[10] = __float2half_rn(a2.z); h[11] = __float2half_rn(a2.w);
    h[12] = __float2half_rn(a3.x); h[13] = __float2half_rn(a3.y);
    h[14] = __float2half_rn(a3.z); h[15] = __float2half_rn(a3.w);
    *(uint4*)(dst + i)     = *(uint4*)h;
    *(uint4*)(dst + i + 8) = *(uint4*)(h + 8);
}

__device__ __forceinline__ void convlm_group(
    const float* __restrict__ src, __half* __restrict__ dst, int k, int g)
{
    int n = g * 8;
    size_t base = (size_t)k * Vdim + n;
    int rc = Vdim - n;
    __half h[8];
    #pragma unroll
    for (int j = 0; j < 8; j++) h[j] = __half(0.f);

    if (rc >= 8) {
        int p = k & 3;
        size_t a0 = base - p;
        if (p == 0) {
            float4 w0 = *(const float4*)(src + a0);
            float4 w1 = *(const float4*)(src + a0 + 4);
            h[0] = __float2half_rn(w0.x); h[1] = __float2half_rn(w0.y);
            h[2] = __float2half_rn(w0.z); h[3] = __float2half_rn(w0.w);
            h[4] = __float2half_rn(w1.x); h[5] = __float2half_rn(w1.y);
            h[6] = __float2half_rn(w1.z); h[7] = __float2half_rn(w1.w);
        } else {
            float4 w0 = *(const float4*)(src + a0);
            float4 w1 = *(const float4*)(src + a0 + 4);
            float4 w2 = *(const float4*)(src + a0 + 8);
            float wnd[12] = {w0.x, w0.y, w0.z, w0.w, w1.x, w1.y, w1.z, w1.w,
                             w2.x, w2.y, w2.z, w2.w};
            switch (p) {
            case 1:
                #pragma unroll
                for (int j = 0; j < 8; j++) h[j] = __float2half_rn(wnd[1 + j]);
                break;
            case 2:
                #pragma unroll
                for (int j = 0; j < 8; j++) h[j] = __float2half_rn(wnd[2 + j]);
                break;
            default:
                #pragma unroll
                for (int j = 0; j < 8; j++) h[j] = __float2half_rn(wnd[3 + j]);
                break;
            }
        }
    } else if (rc > 0) {
        for (int j = 0; j < rc; j++) h[j] = __float2half_rn(src[base + j]);
    }
    *(uint4*)(dst + (size_t)k * VPAD + n) = *(uint4*)h;
}

// ---------------------------------------------------------------------------
// Mega-prologue: ALL weight conversions + embed+ln1 in ONE launch.
// Blocks [0,768): W_attn, [768,1024): W_ap, [1024,2048): W_fc,
// [2048,3072): W_proj, [3072,16384): W_lm, [16384,20480): embed+ln1 rows.
// ---------------------------------------------------------------------------
#define CONV_GRID (3072 + Ddim * LMROWBLK + Mrows)   // 20480

__global__ void __launch_bounds__(256) prologue_kernel(
    const float* __restrict__ Wattn, const float* __restrict__ Wap,
    const float* __restrict__ Wfc,   const float* __restrict__ Wproj,
    const float* __restrict__ Wlm,
    __half* __restrict__ wattn16, __half* __restrict__ wap16,
    __half* __restrict__ wfc16,   __half* __restrict__ wproj16,
    __half* __restrict__ wlm16,
    const int* __restrict__ ids, const float* __restrict__ wte,
    const float* __restrict__ wpe, const float* __restrict__ g1,
    const float* __restrict__ b1, float* __restrict__ hout,
    __half* __restrict__ x16out)
{
    int b = blockIdx.x;
    int t = threadIdx.x;
    if (b < 3072) {
        const float* src;
        __half* dst;
        int lb;
        if (b < 768)       { src = Wattn; dst = wattn16; lb = b; }
        else if (b < 1024) { src = Wap;   dst = wap16;   lb = b - 768; }
        else if (b < 2048) { src = Wfc;   dst = wfc16;   lb = b - 1024; }
        else               { src = Wproj; dst = wproj16; lb = b - 2048; }
        size_t i = ((size_t)lb * 256 + t) * 16;
        conv16_chunk(src, dst, i);
    } else if (b < 3072 + Ddim * LMROWBLK) {
        int bb = b - 3072;
        int k  = bb / LMROWBLK;
        int gb = bb % LMROWBLK;
        int g0 = (gb * 256 + t) * 2;
        if (g0 < NGRP)     convlm_group(Wlm, wlm16, k, g0);
        if (g0 + 1 < NGRP) convlm_group(Wlm, wlm16, k, g0 + 1);
    } else {
        // embed + ln1 for one row
        int row = b - (3072 + Ddim * LMROWBLK);
        int s0  = row & (Sdim - 1);
        int id  = ids[row];
        float4 a = ((const float4*)(wte + (size_t)id * Ddim))[t];
        float4 p = ((const float4*)(wpe + (size_t)s0 * Ddim))[t];
        float4 v = make_float4(a.x + p.x, a.y + p.y, a.z + p.z, a.w + p.w);
        ((float4*)(hout + (size_t)row * Ddim))[t] = v;

        float s = v.x + v.y + v.z + v.w;
        float q = v.x * v.x + v.y * v.y + v.z * v.z + v.w * v.w;
        __shared__ float rs[8], rq[8];
        #pragma unroll
        for (int o = 16; o > 0; o >>= 1) {
            s += __shfl_xor_sync(0xffffffffu, s, o);
            q += __shfl_xor_sync(0xffffffffu, q, o);
        }
        if ((t & 31) == 0) { rs[t >> 5] = s; rq[t >> 5] = q; }
        __syncthreads();
        if (t == 0) {
            float S = 0.f, Q = 0.f;
            #pragma unroll
            for (int i = 0; i < 8; i++) { S += rs[i]; Q += rq[i]; }
            rs[0] = S; rq[0] = Q;
        }
        __syncthreads();
        float mu   = rs[0] * (1.f / Ddim);
        float var  = rq[0] * (1.f / Ddim) - mu * mu;
        float rstd = rsqrtf(var + 1e-5f);
        float4 gg = ((const float4*)g1)[t];
        float4 bb = ((const float4*)b1)[t];
        __half2* o = (__half2*)(x16out + (size_t)row * Ddim + t * 4);
        o[0] = __floats2half2_rn((v.x - mu) * rstd * gg.x + bb.x,
                                 (v.y - mu) * rstd * gg.y + bb.y);
        o[1] = __floats2half2_rn((v.z - mu) * rstd * gg.z + bb.z,
                                 (v.w - mu) * rstd * gg.w + bb.w);
    }
}

// ---------------------------------------------------------------------------
// LayerNorm (fp32 in) -> fp16 out (for ln2 / lnf)
// ---------------------------------------------------------------------------
__global__ void __launch_bounds__(256) ln16_kernel(
    const float* __restrict__ in, const float* __restrict__ g,
    const float* __restrict__ b, __half* __restrict__ out)
{
    int row = blockIdx.x;
    int t = threadIdx.x;
    const float4* xp = (const float4*)(in + (size_t)row * Ddim);
    float4 v = xp[t];
    float s = v.x + v.y + v.z + v.w;
    float q = v.x * v.x + v.y * v.y + v.z * v.z + v.w * v.w;
    __shared__ float rs[8], rq[8];
    #pragma unroll
    for (int o = 16; o > 0; o >>= 1) {
        s += __shfl_xor_sync(0xffffffffu, s, o);
        q += __shfl_xor_sync(0xffffffffu, q, o);
    }
    if ((t & 31) == 0) { rs[t >> 5] = s; rq[t >> 5] = q; }
    __syncthreads();
    if (t == 0) {
        float S = 0.f, Q = 0.f;
        #pragma unroll
        for (int i = 0; i < 8; i++) { S += rs[i]; Q += rq[i]; }
        rs[0] = S; rq[0] = Q;
    }
    __syncthreads();
    float mu   = rs[0] * (1.f / Ddim);
    float var  = rq[0] * (1.f / Ddim) - mu * mu;
    float rstd = rsqrtf(var + 1e-5f);
    float4 gg = ((const float4*)g)[t];
    float4 bb = ((const float4*)b)[t];
    __half2* o = (__half2*)(out + (size_t)row * Ddim + t * 4);
    o[0] = __floats2half2_rn((v.x - mu) * rstd * gg.x + bb.x,
                             (v.y - mu) * rstd * gg.y + bb.y);
    o[1] = __floats2half2_rn((v.z - mu) * rstd * gg.z + bb.z,
                             (v.w - mu) * rstd * gg.w + bb.w);
}

// ---------------------------------------------------------------------------
// fp16 GEMM (fp32 acc): 128 threads (4 warps 2x2), CTA 128x128, warp 64x64,
// 3-stage cp.async ring, 2 CTAs/SM. (verified R11 — used for ALL GEMMs)
// ---------------------------------------------------------------------------
#define APh 40
#define BPh 136
#define ASZ (128 * APh)
#define BSZ (32 * BPh)
#define STGh (ASZ + BSZ)
#define GSMEM (3 * STGh * 2)     // 56832 B

template<bool HAS_BIAS, bool DO_GELU, bool HAS_RES, bool OUT16>
__global__ void __launch_bounds__(128, 2) gemm16_kernel(
    const __half* __restrict__ A, const __half* __restrict__ W,
    const float* __restrict__ bias, const float* __restrict__ res,
    void* __restrict__ Cv, int M, int N, int K, int ldw)
{
    extern __shared__ __half sh[];
    const uint32_t sb = smem_u32(sh);

    const int tid  = threadIdx.x;
    const int wid  = tid >> 5;
    const int lane = tid & 31;
    const int wm   = (wid >> 1) * 64;
    const int wn   = (wid & 1) * 64;
    const int lr   = lane >> 2;
    const int lc   = lane & 3;
    const int bm   = blockIdx.x * 128;
    const int bn   = blockIdx.y * 128;

    const int am  = tid >> 2, akc = tid & 3;
    const int bk  = tid >> 4, bnc = tid & 15;

    auto issue = [&](int kb) {
        const int s = kb % 3;
        const uint32_t as = sb + (uint32_t)(s * STGh) * 2;
        const uint32_t bs = as + ASZ * 2;
        const int k0 = kb * 32;
        #pragma unroll
        for (int i = 0; i < 4; i++) {
            int m = am + i * 32;
            const __half* src = A + (size_t)(bm + m) * K + k0 + akc * 8;
            uint32_t dst = as + (uint32_t)(m * APh + akc * 8) * 2;
            asm volatile("cp.async.cg.shared.global [%0], [%1], 16;"
                         :: "r"(dst), "l"(src));
        }
        #pragma unroll
        for (int i = 0; i < 4; i++) {
            int k = bk + i * 8;
            const __half* src = W + (size_t)(k0 + k) * ldw + bn + bnc * 8;
            uint32_t dst = bs + (uint32_t)(k * BPh + bnc * 8) * 2;
            asm volatile("cp.async.cg.shared.global [%0], [%1], 16;"
                         :: "r"(dst), "l"(src));
        }
        asm volatile("cp.async.commit_group;");
    };

    float acc[4][8][4];
    #pragma unroll
    for (int i = 0; i < 4; i++)
        #pragma unroll
        for (int j = 0; j < 8; j++)
            #pragma unroll
            for (int e = 0; e < 4; e++) acc[i][j][e] = 0.f;

    const int nk = K / 32;
    issue(0);
    issue(1);

    for (int kb = 0; kb < nk; kb++) {
        if (kb + 1 < nk) asm volatile("cp.async.wait_group 1;");
        else             asm volatile("cp.async.wait_group 0;");
        __syncthreads();
        if (kb + 2 < nk) issue(kb + 2);

        const int s = kb % 3;
        const uint32_t as = sb + (uint32_t)(s * STGh) * 2;
        const uint32_t bs = as + ASZ * 2;

        #pragma unroll
        for (int ks = 0; ks < 2; ks++) {
            const int kk = ks * 16;
            uint32_t afr[4][4];
            #pragma unroll
            for (int mt = 0; mt < 4; mt++) {
                uint32_t a = as + (uint32_t)((wm + mt * 16 + (lane & 15)) * APh
                                             + kk + 8 * (lane >> 4)) * 2;
                LDSM4(afr[mt][0], afr[mt][1], afr[mt][2], afr[mt][3], a);
            }
            uint32_t bfr[8][2];
            #pragma unroll
            for (int p = 0; p < 4; p++) {
                int ntp = p * 2;
                uint32_t a = bs + (uint32_t)((kk + (lane & 7) + 8 * ((lane >> 3) & 1)) * BPh
                                             + wn + (ntp + (lane >> 4)) * 8) * 2;
                LDSM4T(bfr[ntp][0], bfr[ntp][1], bfr[ntp + 1][0], bfr[ntp + 1][1], a);
            }
            #pragma unroll
            for (int mt = 0; mt < 4; mt++)
                #pragma unroll
                for (int nt = 0; nt < 8; nt++)
                    MMA16816(acc[mt][nt], afr[mt], bfr[nt][0], bfr[nt][1]);
        }
    }

    float* Cf = (float*)Cv;
    __half* Ch = (__half*)Cv;
    const bool neven = ((N & 1) == 0);
    #pragma unroll
    for (int mt = 0; mt < 4; mt++) {
        int row0 = bm + wm + mt * 16 + lr;
        #pragma unroll
        for (int nt = 0; nt < 8; nt++) {
            int col0 = bn + wn + nt * 8 + lc * 2;
            #pragma unroll
            for (int half_ = 0; half_ < 2; half_++) {
                int row = row0 + half_ * 8;
                float v0 = acc[mt][nt][half_ * 2];
                float v1 = acc[mt][nt][half_ * 2 + 1];
                if (HAS_BIAS) { v0 += bias[col0]; v1 += bias[col0 + 1]; }
                if (DO_GELU)  { v0 = gelu_new_f(v0); v1 = gelu_new_f(v1); }
                size_t off = (size_t)row * (size_t)N + col0;
                if (HAS_RES) {
                    if (col0 < N)     v0 += res[off];
                    if (col0 + 1 < N) v1 += res[off + 1];
                }
                if (neven && col0 + 1 < N) {
                    if (OUT16) *(__half2*)(Ch + off) = __floats2half2_rn(v0, v1);
                    else       *(float2*)(Cf + off) = make_float2(v0, v1);
                } else {
                    if (col0 < N) {
                        if (OUT16) Ch[off] = __float2half_rn(v0);
                        else       Cf[off] = v0;
                    }
                    if (col0 + 1 < N) {
                        if (OUT16) Ch[off + 1] = __float2half_rn(v1);
                        else       Cf[off + 1] = v1;
                    }
                }
            }
        }
    }
}

// ---------------------------------------------------------------------------
// Tensor-core flash attention (causal), fp16 mma, fp32 softmax, 2 CTAs/SM.
// ---------------------------------------------------------------------------
#define FP 72
#define FLASH16_SMEM ((128 * FP + 4 * 64 * FP) * 2)   // 55296 B

__global__ void __launch_bounds__(256, 2) flashtc_kernel(
    const __half* __restrict__ qkv, __half* __restrict__ ao)
{
    extern __shared__ __half fsm[];
    const uint32_t sb   = smem_u32(fsm);
    const uint32_t qs_b = sb;
    const uint32_t ks_b = sb + 128 * FP * 2;
    const uint32_t vs_b = ks_b + 2 * 64 * FP * 2;
    __half* Qs = fsm;

    const int qt  = (int)gridDim.x - 1 - (int)blockIdx.x;
    const int bh  = blockIdx.y;
    const int b   = bh >> 4;
    const int h   = bh & 15;
    const int tid = threadIdx.x;
    const int wid = tid >> 5;
    const int lane = tid & 31;
    const int lr  = lane >> 2;
    const int lc  = lane & 3;
    const size_t base = (size_t)b * Sdim * 3072 + (size_t)h * 64;

    const __half2 kscale = __floats2half2_rn(0.125f, 0.125f);
    #pragma unroll
    for (int i = 0; i < 4; i++) {
        int task = tid + i * 256;
        int row = task >> 3, ch = task & 7;
        uint4 u = *(const uint4*)(qkv + base + (size_t)(qt * 128 + row) * 3072 + ch * 8);
        __half2* hp = (__half2*)&u;
        #pragma unroll
        for (int j = 0; j < 4; j++) hp[j] = __hmul2(hp[j], kscale);
        *(uint4*)&Qs[row * FP + ch * 8] = u;
    }

    auto issue = [&](int kt) {
        const int s = kt & 1;
        #pragma unroll
        for (int i = 0; i < 2; i++) {
            int task = tid + i * 256;
            int row = task >> 3, ch = task & 7;
            const __half* sk = qkv + base + 1024 + (size_t)(kt * 64 + row) * 3072 + ch * 8;
            const __half* sv = qkv + base + 2048 + (size_t)(kt * 64 + row) * 3072 + ch * 8;
            uint32_t dk = ks_b + (uint32_t)(s * 64 * FP + row * FP + ch * 8) * 2;
            uint32_t dv = vs_b + (uint32_t)(s * 64 * FP + row * FP + ch * 8) * 2;
            asm volatile("cp.async.cg.shared.global [%0], [%1], 16;" :: "r"(dk), "l"(sk));
            asm volatile("cp.async.cg.shared.global [%0], [%1], 16;" :: "r"(dv), "l"(sv));
        }
        asm volatile("cp.async.commit_group;");
    };

    const int ktn = 2 * qt + 2;
    issue(0);
    issue(1);
    __syncthreads();

    uint32_t qf[4][4];
    {
        int row = wid * 16 + (lane & 15);
        int cof = 8 * (lane >> 4);
        #pragma unroll
        for (int kc = 0; kc < 4; kc++) {
            uint32_t a = qs_b + (uint32_t)(row * FP + kc * 16 + cof) * 2;
            LDSM4(qf[kc][0], qf[kc][1], qf[kc][2], qf[kc][3], a);
        }
    }

    float o[8][4];
    #pragma unroll
    for (int nt = 0; nt < 8; nt++)
        #pragma unroll
        for (int e = 0; e < 4; e++) o[nt][e] = 0.f;
    float m0 = -1e30f, m1 = -1e30f, l0 = 0.f, l1 = 0.f;
    const int qg0 = qt * 128 + wid * 16 + lr;

    for (int kt = 0; kt < ktn; kt++) {
        if (kt + 1 < ktn) asm volatile("cp.async.wait_group 1;");
        else              asm volatile("cp.async.wait_group 0;");
        __syncthreads();

        const int s = kt & 1;
        const uint32_t kb_ = ks_b + (uint32_t)(s * 64 * FP) * 2;
        const uint32_t vb_ = vs_b + (uint32_t)(s * 64 * FP) * 2;

        float sc[8][4];
        #pragma unroll
        for (int nt = 0; nt < 8; nt++)
            #pragma unroll
            for (int e = 0; e < 4; e++) sc[nt][e] = 0.f;
        const int krow = (lane & 7) + 8 * (lane >> 4);
        const int koff = 8 * ((lane >> 3) & 1);
        #pragma unroll
        for (int kc = 0; kc < 4; kc++) {
            #pragma unroll
            for (int np = 0; np < 4; np++) {
                uint32_t a = kb_ + (uint32_t)((np * 16 + krow) * FP + kc * 16 + koff) * 2;
                uint32_t b0, b1, b2, b3;
                LDSM4(b0, b1, b2, b3, a);
                MMA16816(sc[2 * np], qf[kc], b0, b1);
                MMA16816(sc[2 * np + 1], qf[kc], b2, b3);
            }
        }

        const bool diag = (kt >= 2 * qt);
        float tmax0 = -1e30f, tmax1 = -1e30f;
        #pragma unroll
        for (int nt = 0; nt < 8; nt++) {
            #pragma unroll
            for (int e = 0; e < 4; e++) {
                if (diag) {
                    int key = kt * 64 + nt * 8 + 2 * lc + (e & 1);
                    int qg  = qg0 + (e >= 2 ? 8 : 0);
                    if (key > qg) sc[nt][e] = -1e30f;
                }
                if (e < 2) tmax0 = fmaxf(tmax0, sc[nt][e]);
                else       tmax1 = fmaxf(tmax1, sc[nt][e]);
            }
        }
        tmax0 = fmaxf(tmax0, __shfl_xor_sync(0xffffffffu, tmax0, 1));
        tmax0 = fmaxf(tmax0, __shfl_xor_sync(0xffffffffu, tmax0, 2));
        tmax1 = fmaxf(tmax1, __shfl_xor_sync(0xffffffffu, tmax1, 1));
        tmax1 = fmaxf(tmax1, __shfl_xor_sync(0xffffffffu, tmax1, 2));
        float mn0 = fmaxf(m0, tmax0), mn1 = fmaxf(m1, tmax1);
        float cr0 = __expf(m0 - mn0), cr1 = __expf(m1 - mn1);
        float ps0 = 0.f, ps1 = 0.f;
        #pragma unroll
        for (int nt = 0; nt < 8; nt++) {
            sc[nt][0] = __expf(sc[nt][0] - mn0);
            sc[nt][1] = __expf(sc[nt][1] - mn0);
            sc[nt][2] = __expf(sc[nt][2] - mn1);
            sc[nt][3] = __expf(sc[nt][3] - mn1);
            ps0 += sc[nt][0] + sc[nt][1];
            ps1 += sc[nt][2] + sc[nt][3];
        }
        ps0 += __shfl_xor_sync(0xffffffffu, ps0, 1);
        ps0 += __shfl_xor_sync(0xffffffffu, ps0, 2);
        ps1 += __shfl_xor_sync(0xffffffffu, ps1, 1);
        ps1 += __shfl_xor_sync(0xffffffffu, ps1, 2);
        l0 = l0 * cr0 + ps0;  m0 = mn0;
        l1 = l1 * cr1 + ps1;  m1 = mn1;
        #pragma unroll
        for (int nt = 0; nt < 8; nt++) {
            o[nt][0] *= cr0; o[nt][1] *= cr0;
            o[nt][2] *= cr1; o[nt][3] *= cr1;
        }

        uint32_t pf[4][4];
        #pragma unroll
        for (int kc = 0; kc < 4; kc++) {
            __half2 h0 = __floats2half2_rn(sc[2 * kc][0], sc[2 * kc][1]);
            __half2 h1 = __floats2half2_rn(sc[2 * kc][2], sc[2 * kc][3]);
            __half2 h2 = __floats2half2_rn(sc[2 * kc + 1][0], sc[2 * kc + 1][1]);
            __half2 h3 = __floats2half2_rn(sc[2 * kc + 1][2], sc[2 * kc + 1][3]);
            pf[kc][0] = *(uint32_t*)&h0;
            pf[kc][1] = *(uint32_t*)&h1;
            pf[kc][2] = *(uint32_t*)&h2;
            pf[kc][3] = *(uint32_t*)&h3;
        }

        const int vrow = (lane & 7) + 8 * ((lane >> 3) & 1);
        const int vcof = (lane >> 4);
        #pragma unroll
        for (int kc = 0; kc < 4; kc++) {
            #pragma unroll
            for (int np = 0; np < 4; np++) {
                uint32_t a = vb_ + (uint32_t)((kc * 16 + vrow) * FP + (np * 2 + vcof) * 8) * 2;
                uint32_t b0, b1, b2, b3;
                LDSM4T(b0, b1, b2, b3, a);
                MMA16816(o[2 * np], pf[kc], b0, b1);
                MMA16816(o[2 * np + 1], pf[kc], b2, b3);
            }
        }

        if (kt + 2 < ktn) {
            __syncthreads();
            issue(kt + 2);
        }
    }

    float i0 = 1.f / l0, i1 = 1.f / l1;
    size_t r0 = (size_t)(b * Sdim + qt * 128 + wid * 16 + lr) * Ddim + h * 64;
    size_t r1 = r0 + 8 * Ddim;
    #pragma unroll
    for (int nt = 0; nt < 8; nt++) {
        int col = nt * 8 + 2 * lc;
        *(__half2*)(ao + r0 + col) = __floats2half2_rn(o[nt][0] * i0, o[nt][1] * i0);
        *(__half2*)(ao + r1 + col) = __floats2half2_rn(o[nt][2] * i1, o[nt][3] * i1);
    }
}

// ---------------------------------------------------------------------------
// Launch sequence
// ---------------------------------------------------------------------------
extern "C" void kernel_launch(void* const* d_in, const int* in_sizes, int n_in,
                              void* d_out, int out_size)
{
    const int*   ids    = (const int*)d_in[0];
    const float* wte    = (const float*)d_in[1];
    const float* wpe    = (const float*)d_in[2];
    const float* ln1_g  = (const float*)d_in[3];
    const float* ln1_b  = (const float*)d_in[4];
    const float* W_attn = (const float*)d_in[5];
    const float* b_attn = (const float*)d_in[6];
    const float* W_ap   = (const float*)d_in[7];
    const float* b_ap   = (const float*)d_in[8];
    const float* ln2_g  = (const float*)d_in[9];
    const float* ln2_b  = (const float*)d_in[10];
    const float* W_fc   = (const float*)d_in[11];
    const float* b_fc   = (const float*)d_in[12];
    const float* W_proj = (const float*)d_in[13];
    const float* b_proj = (const float*)d_in[14];
    const float* lnf_g  = (const float*)d_in[15];
    const float* lnf_b  = (const float*)d_in[16];
    const float* W_lm   = (const float*)d_in[17];
    float* out = (float*)d_out;

    float *h;
    __half *qkv16, *x16, *ao16, *fc16, *wattn16, *wap16, *wfc16, *wproj16, *wlm16;
    cudaGetSymbolAddress((void**)&h,       g_h);
    cudaGetSymbolAddress((void**)&qkv16,   g_qkv16);
    cudaGetSymbolAddress((void**)&x16,     g_x16);
    cudaGetSymbolAddress((void**)&ao16,    g_ao16);
    cudaGetSymbolAddress((void**)&fc16,    g_fc16);
    cudaGetSymbolAddress((void**)&wattn16, g_wattn16);
    cudaGetSymbolAddress((void**)&wap16,   g_wap16);
    cudaGetSymbolAddress((void**)&wfc16,   g_wfc16);
    cudaGetSymbolAddress((void**)&wproj16, g_wproj16);
    cudaGetSymbolAddress((void**)&wlm16,   g_wlm16);

    cudaFuncSetAttribute(flashtc_kernel,
                         cudaFuncAttributeMaxDynamicSharedMemorySize, FLASH16_SMEM);
    cudaFuncSetAttribute(gemm16_kernel<true, false, false, true>,
                         cudaFuncAttributeMaxDynamicSharedMemorySize, GSMEM);
    cudaFuncSetAttribute(gemm16_kernel<true, false, true, false>,
                         cudaFuncAttributeMaxDynamicSharedMemorySize, GSMEM);
    cudaFuncSetAttribute(gemm16_kernel<true, true, false, true>,
                         cudaFuncAttributeMaxDynamicSharedMemorySize, GSMEM);
    cudaFuncSetAttribute(gemm16_kernel<false, false, false, false>,
                         cudaFuncAttributeMaxDynamicSharedMemorySize, GSMEM);

    // all conversions + embed+ln1 in ONE launch
    prologue_kernel<<<CONV_GRID, 256>>>(
        W_attn, W_ap, W_fc, W_proj, W_lm,
        wattn16, wap16, wfc16, wproj16, wlm16,
        ids, wte, wpe, ln1_g, ln1_b, h, x16);
    // qkv = x @ W_attn + b_attn (fp16 out)   N=3072
    gemm16_kernel<true, false, false, true><<<dim3(32, 24), 128, GSMEM>>>(
        x16, wattn16, b_attn, nullptr, qkv16, Mrows, 3 * Ddim, Ddim, 3 * Ddim);
    flashtc_kernel<<<dim3(16, 32), 256, FLASH16_SMEM>>>(qkv16, ao16);
    // h = h + ao @ W_ap + b_ap               N=1024
    gemm16_kernel<true, false, true, false><<<dim3(32, 8), 128, GSMEM>>>(
        ao16, wap16, b_ap, h, h, Mrows, Ddim, Ddim, Ddim);
    ln16_kernel<<<Mrows, 256>>>(h, ln2_g, ln2_b, x16);
    // fc = gelu(x @ W_fc + b_fc) (fp16 out)  N=4096
    gemm16_kernel<true, true, false, true><<<dim3(32, 32), 128, GSMEM>>>(
        x16, wfc16, b_fc, nullptr, fc16, Mrows, 4 * Ddim, Ddim, 4 * Ddim);
    // h = h + fc @ W_proj + b_proj           N=1024
    gemm16_kernel<true, false, true, false><<<dim3(32, 8), 128, GSMEM>>>(
        fc16, wproj16, b_proj, h, h, Mrows, Ddim, 4 * Ddim, Ddim);
    ln16_kernel<<<Mrows, 256>>>(h, lnf_g, lnf_b, x16);
    // logits = x @ W_lm (fp32 out)           N=50257
    gemm16_kernel<false, false, false, false><<<dim3(32, 393), 128, GSMEM>>>(
        x16, wlm16, nullptr, nullptr, out, Mrows, Vdim, Ddim, VPAD);
}